// round 16
// baseline (speedup 1.0000x reference)
#include <cuda_runtime.h>
#include <cuda_fp16.h>
#include <cstdint>

// Problem shape (fixed by the dataset)
#define BB   4
#define SS   2048
#define DD   1024
#define HH   16
#define DHD  64
#define D3   3072
#define MTOK (BB*SS)   // 8192 tokens

// Scratch (allocation-free: __device__ globals)
__device__ __half g_Qh[BB*HH*SS*DHD];
__device__ __half g_Kh[BB*HH*SS*DHD];
__device__ __half g_Vh[BB*HH*SS*DHD];
__device__ __half g_Oh[MTOK*DD];    // attention output (fp16)
__device__ float  g_Y[MTOK*DD];     // o-proj + residual (fp32)
__device__ __half g_Xh[MTOK*DD];    // fp16 copy of x0
__device__ __half g_WiTh[D3*DD];    // fp16 W_in^T  [N=3072][K=1024]
__device__ __half g_WoTh[DD*DD];    // fp16 W_o^T   [N=1024][K=1024]

// ---------------------------------------------------------------------------
// helpers
// ---------------------------------------------------------------------------
__device__ __forceinline__ void cp16(unsigned smem_addr, const void* gptr) {
    asm volatile("cp.async.cg.shared.global [%0], [%1], 16;\n"
                 :: "r"(smem_addr), "l"(gptr));
}
__device__ __forceinline__ void cp_commit() {
    asm volatile("cp.async.commit_group;\n");
}
template<int N>
__device__ __forceinline__ void cp_wait() {
    asm volatile("cp.async.wait_group %0;\n" :: "n"(N));
}
// fp16 MMA: m16n8k16, fp32 accumulate.
__device__ __forceinline__ void mma_f16(float* d,
                                        const unsigned* a, const unsigned* b)
{
    asm volatile(
        "mma.sync.aligned.m16n8k16.row.col.f32.f16.f16.f32 "
        "{%0,%1,%2,%3}, {%4,%5,%6,%7}, {%8,%9}, {%0,%1,%2,%3};"
        : "+f"(d[0]), "+f"(d[1]), "+f"(d[2]), "+f"(d[3])
        : "r"(a[0]), "r"(a[1]), "r"(a[2]), "r"(a[3]),
          "r"(b[0]), "r"(b[1]));
}
__device__ __forceinline__ void ldsm_x4(unsigned* r, unsigned addr) {
    asm volatile(
        "ldmatrix.sync.aligned.m8n8.x4.shared.b16 {%0,%1,%2,%3}, [%4];"
        : "=r"(r[0]), "=r"(r[1]), "=r"(r[2]), "=r"(r[3]) : "r"(addr));
}
__device__ __forceinline__ void ldsm_x4_t(unsigned* r, unsigned addr) {
    asm volatile(
        "ldmatrix.sync.aligned.m8n8.x4.trans.shared.b16 {%0,%1,%2,%3}, [%4];"
        : "=r"(r[0]), "=r"(r[1]), "=r"(r[2]), "=r"(r[3]) : "r"(addr));
}
__device__ __forceinline__ float fexp2(float x) {
    float r;
    asm("ex2.approx.f32 %0, %1;" : "=f"(r) : "f"(x));
    return r;
}
#define QSCALE 0.18033688f   // 0.125 * log2(e): softmax in base-2 domain

// ---------------------------------------------------------------------------
// conversion kernels
// ---------------------------------------------------------------------------
__global__ void f2h(const float* __restrict__ in, __half* __restrict__ out)
{
    const int i = blockIdx.x * 256 + threadIdx.x;
    float4 v = ((const float4*)in)[i];
    ((__half2*)out)[i * 2]     = __floats2half2_rn(v.x, v.y);
    ((__half2*)out)[i * 2 + 1] = __floats2half2_rn(v.z, v.w);
}

// W[K][N] fp32 row-major -> Wt[N][K] fp16
__global__ void transpose_cvt(const float* __restrict__ W, __half* __restrict__ Wt,
                              int K, int N)
{
    __shared__ float t[32][33];
    const int k0 = blockIdx.y * 32;
    const int n0 = blockIdx.x * 32;
    const int tx = threadIdx.x;
#pragma unroll
    for (int i = threadIdx.y; i < 32; i += 8)
        t[i][tx] = W[(size_t)(k0 + i) * N + n0 + tx];
    __syncthreads();
#pragma unroll
    for (int i = threadIdx.y; i < 32; i += 8)
        Wt[(size_t)(n0 + i) * K + k0 + tx] = __float2half(t[tx][i]);
}

// ---------------------------------------------------------------------------
// fp16 tensor-core GEMM: C[M,N] = A @ B, A[M][K] and Bt[N][K] fp16 k-major.
// Block tile 128(M) x 256(N), 8 warps (2x4), warp tile 64x64
// -> per ks-step: 8 LDSM : 32 MMA (4:1 ratio, 2x the R15 tile).
// K-tile 32, 3-stage cp.async ring, prefetch distance 2, ONE barrier/ktile.
// smem rows stride 40 halves (80B) -> LDSM rows on distinct banks.
// MODE 0: scatter fp16 epilogue to g_Qh/g_Kh/g_Vh. MODE 1: + R -> g_Y fp32.
// ---------------------------------------------------------------------------
#define GH_ST 40
#define GEMM_SMEM_BYTES (3 * (128 + 256) * GH_ST * 2)   // 92,160 B

template<int MODE>
__global__ void __launch_bounds__(256)
gemm_f16(const __half* __restrict__ A, const __half* __restrict__ Bt,
         const float* __restrict__ R, int M, int N, int K)
{
    extern __shared__ __half smh[];
    __half* As = smh;                          // 3 stages x 128*GH_ST halves
    __half* Bs = smh + 3 * 128 * GH_ST;        // 3 stages x 256*GH_ST halves

    const int tid    = threadIdx.x;
    const int warp   = tid >> 5;
    const int lane   = tid & 31;
    const int g      = lane >> 2;
    const int tig    = lane & 3;
    const int warp_m = warp >> 2;              // 0..1
    const int warp_n = warp & 3;               // 0..3
    const int row_w  = warp_m * 64;
    const int col_w  = warp_n * 64;

    const int bm = blockIdx.y * 128;
    const int bn = blockIdx.x * 256;

    const unsigned as_base = (unsigned)__cvta_generic_to_shared(As);
    const unsigned bs_base = (unsigned)__cvta_generic_to_shared(Bs);

    const int a_lrow = row_w + (lane & 15);
    const int a_lcof = (lane >> 4) * 8;                      // halves
    const int b_lrow = col_w + ((lane >> 4) << 3) + (lane & 7);
    const int b_lcof = ((lane >> 3) & 1) * 8;                // halves

    float acc[4][8][4];
#pragma unroll
    for (int mi = 0; mi < 4; mi++)
#pragma unroll
        for (int ni = 0; ni < 8; ni++)
#pragma unroll
            for (int r = 0; r < 4; r++) acc[mi][ni][r] = 0.f;

    auto prefetch = [&](int stage, int k0) {
        // A: 128 rows x 32 halves = 512 cp16; 2 per thread
#pragma unroll
        for (int t = 0; t < 2; t++) {
            const int idx = tid + t * 256;
            const int r   = idx >> 2;
            const int c   = (idx & 3) * 8;
            cp16(as_base + (unsigned)((stage * 128 + r) * GH_ST + c) * 2,
                 A + (size_t)(bm + r) * K + k0 + c);
        }
        // B: 256 rows x 32 halves = 1024 cp16; 4 per thread
#pragma unroll
        for (int t = 0; t < 4; t++) {
            const int idx = tid + t * 256;
            const int r   = idx >> 2;
            const int c   = (idx & 3) * 8;
            cp16(bs_base + (unsigned)((stage * 256 + r) * GH_ST + c) * 2,
                 Bt + (size_t)(bn + r) * K + k0 + c);
        }
        cp_commit();
    };

    const int KT = K / 32;
    prefetch(0, 0);
    prefetch(1, 32);

    int buf = 0;
    for (int kt = 0; kt < KT; kt++) {
        cp_wait<1>();
        __syncthreads();

        if (kt + 2 < KT) {
            int nb = buf + 2; if (nb >= 3) nb -= 3;
            prefetch(nb, (kt + 2) * 32);
        } else {
            cp_commit();
        }

        const unsigned asu = as_base + (unsigned)(buf * 128 * GH_ST) * 2;
        const unsigned bsu = bs_base + (unsigned)(buf * 256 * GH_ST) * 2;

#pragma unroll
        for (int ks = 0; ks < 32; ks += 16) {
            unsigned af[4][4];
#pragma unroll
            for (int mi = 0; mi < 4; mi++)
                ldsm_x4(af[mi],
                        asu + (unsigned)((a_lrow + mi * 16) * GH_ST
                                         + ks + a_lcof) * 2);
            unsigned bf[4][4];
#pragma unroll
            for (int nip = 0; nip < 4; nip++)
                ldsm_x4(bf[nip],
                        bsu + (unsigned)((b_lrow + nip * 16) * GH_ST
                                         + ks + b_lcof) * 2);
#pragma unroll
            for (int mi = 0; mi < 4; mi++) {
#pragma unroll
                for (int nip = 0; nip < 4; nip++) {
                    mma_f16(acc[mi][nip * 2],     af[mi], &bf[nip][0]);
                    mma_f16(acc[mi][nip * 2 + 1], af[mi], &bf[nip][2]);
                }
            }
        }
        if (++buf == 3) buf = 0;
    }

    if (MODE == 0) {
        // fp16 scatter: pairs never straddle a Q/K/V segment (boundaries %64)
#pragma unroll
        for (int mi = 0; mi < 4; mi++) {
#pragma unroll
            for (int ni = 0; ni < 8; ni++) {
#pragma unroll
                for (int rr = 0; rr < 2; rr++) {
                    const int row = bm + row_w + mi * 16 + g + rr * 8;
                    const int bb  = row >> 11;
                    const int sl  = row & 2047;
                    const int e   = bn + col_w + ni * 8 + 2 * tig;
                    const int hh  = e / 192;
                    const int r   = e - hh * 192;
                    const int base = ((bb * HH + hh) * SS + sl) * DHD;
                    const __half2 v = __floats2half2_rn(acc[mi][ni][rr * 2 + 0],
                                                        acc[mi][ni][rr * 2 + 1]);
                    if (r < 64)        *(__half2*)&g_Qh[base + r]       = v;
                    else if (r < 128)  *(__half2*)&g_Kh[base + r - 64]  = v;
                    else               *(__half2*)&g_Vh[base + r - 128] = v;
                }
            }
        }
    } else {
#pragma unroll
        for (int mi = 0; mi < 4; mi++) {
#pragma unroll
            for (int ni = 0; ni < 8; ni++) {
#pragma unroll
                for (int rr = 0; rr < 2; rr++) {
                    const int row = bm + row_w + mi * 16 + g + rr * 8;
                    const int col = bn + col_w + ni * 8 + 2 * tig;
                    float2 rv = *(const float2*)(R + (size_t)row * DD + col);
                    float2 o;
                    o.x = acc[mi][ni][rr * 2 + 0] + rv.x;
                    o.y = acc[mi][ni][rr * 2 + 1] + rv.y;
                    *(float2*)(g_Y + (size_t)row * DD + col) = o;
                }
            }
        }
    }
}

// ---------------------------------------------------------------------------
// fp16 MMA flash attention, causal, base-2 softmax (fp32 accum/softmax).
// 256 threads, 8 warps x 32 q-rows (256 q-rows/block), K-tile 64 keys,
// 2-stage cp.async. All fragments via ldmatrix (V via .trans).
// (R15-passing, unchanged apart from dead-code removal)
// ---------------------------------------------------------------------------
#define KS_ST 72
#define VS_ST 72
#define PS_ST 72
#define QROWS 256
#define ATTN_SMEM_BYTES ((2*64*KS_ST + 2*64*VS_ST + 8*32*PS_ST) * 2)

__global__ void __launch_bounds__(256, 1)
attn_mma()
{
    extern __shared__ __half smha[];
    __half* Ks0 = smha;                           // also stages Q (128*KS_ST)
    __half* Vs0 = smha + 2 * 64 * KS_ST;
    __half* Ps  = smha + 2 * 64 * KS_ST + 2 * 64 * VS_ST
                       + (threadIdx.x >> 5) * 32 * PS_ST;

    const int b    = blockIdx.z;
    const int h    = blockIdx.y;
    const int qt   = gridDim.x - 1 - blockIdx.x;   // heavy blocks first
    const int tid  = threadIdx.x;
    const int warp = tid >> 5;                     // 0..7
    const int lane = tid & 31;
    const int g    = lane >> 2;
    const int tig  = lane & 3;

    const __half* Qp = g_Qh + (size_t)(b * HH + h) * SS * DHD;
    const __half* Kp = g_Kh + (size_t)(b * HH + h) * SS * DHD;
    const __half* Vp = g_Vh + (size_t)(b * HH + h) * SS * DHD;

    const unsigned ks_base = (unsigned)__cvta_generic_to_shared(Ks0);
    const unsigned vs_base = (unsigned)__cvta_generic_to_shared(Vs0);
    const unsigned ps_base = (unsigned)__cvta_generic_to_shared(Ps);

    const int a_lrow = lane & 15;                          // A frags (Q, P)
    const int a_lcof = (lane >> 4) * 8;
    const int k_lrow = ((lane >> 4) << 3) + (lane & 7);    // K B-frags
    const int k_lcof = ((lane >> 3) & 1) * 8;
    const int v_lrow = (lane & 7) + ((lane >> 3) & 1) * 8; // V B-frags (.trans)
    const int v_ncof = (lane >> 4) * 8;

    // ---- stage Q (two 128-row passes through K buffer), pre-scaled fp16 ----
    unsigned qf[4][2][4];    // [k-chunk][mi][reg]
#pragma unroll
    for (int phase = 0; phase < 2; phase++) {
        __half* Qs = Ks0;    // 128 * KS_ST halves = the 2-stage K region
#pragma unroll
        for (int t = 0; t < 8; t++) {
            const int idx = tid + t * 256;
            const int r   = idx >> 4;
            const int c   = (idx & 15) << 2;
            const __half2* src = (const __half2*)(Qp +
                (size_t)(qt * QROWS + phase * 128 + r) * DHD + c);
            __half2 h0 = src[0], h1 = src[1];
            float2 f0 = __half22float2(h0), f1 = __half22float2(h1);
            *(__half2*)&Qs[r * KS_ST + c]     = __floats2half2_rn(f0.x * QSCALE, f0.y * QSCALE);
            *(__half2*)&Qs[r * KS_ST + c + 2] = __floats2half2_rn(f1.x * QSCALE, f1.y * QSCALE);
        }
        __syncthreads();
        if ((warp >> 2) == phase) {
            const int r0 = (warp & 3) * 32;
#pragma unroll
            for (int kc = 0; kc < 4; kc++)
#pragma unroll
                for (int mi = 0; mi < 2; mi++)
                    ldsm_x4(qf[kc][mi],
                            ks_base + (unsigned)((r0 + mi * 16 + a_lrow) * KS_ST
                                                 + kc * 16 + a_lcof) * 2);
        }
        __syncthreads();
    }

    auto prefetch = [&](int stage, int kt) {
#pragma unroll
        for (int t = 0; t < 2; t++) {
            const int idx = tid + t * 256;
            const int r   = idx >> 3;
            const int c   = (idx & 7) * 8;
            cp16(ks_base + (unsigned)(stage * 64 * KS_ST + r * KS_ST + c) * 2,
                 Kp + (size_t)(kt * 64 + r) * DHD + c);
        }
#pragma unroll
        for (int t = 0; t < 2; t++) {
            const int idx = tid + t * 256;
            const int r   = idx >> 3;
            const int c   = (idx & 7) * 8;
            cp16(vs_base + (unsigned)(stage * 64 * VS_ST + r * VS_ST + c) * 2,
                 Vp + (size_t)(kt * 64 + r) * DHD + c);
        }
        cp_commit();
    };

    float oacc[8][8];
#pragma unroll
    for (int nt = 0; nt < 8; nt++)
#pragma unroll
        for (int r = 0; r < 8; r++) oacc[nt][r] = 0.f;

    float m[4], l[4];
#pragma unroll
    for (int i = 0; i < 4; i++) { m[i] = -1e30f; l[i] = 0.f; }

    const int kt_end = 4 * qt + 3;                 // inclusive
    prefetch(0, 0);

    for (int kt = 0; kt <= kt_end; kt++) {
        if (kt < kt_end) prefetch((kt + 1) & 1, kt + 1);
        else             cp_commit();
        cp_wait<1>();
        __syncthreads();

        const bool active = (kt * 64 <= qt * QROWS + warp * 32 + 31);
        if (active) {
            const unsigned ksu = ks_base + (unsigned)((kt & 1) * 64 * KS_ST) * 2;
            const unsigned vsu = vs_base + (unsigned)((kt & 1) * 64 * VS_ST) * 2;

            float sacc[8][8];
#pragma unroll
            for (int nt = 0; nt < 8; nt++)
#pragma unroll
                for (int r = 0; r < 8; r++) sacc[nt][r] = 0.f;

            // ---- S = Q @ K^T ----
#pragma unroll
            for (int kc = 0; kc < 4; kc++) {
#pragma unroll
                for (int ntp = 0; ntp < 4; ntp++) {
                    unsigned kf[4];
                    ldsm_x4(kf, ksu + (unsigned)((ntp * 16 + k_lrow) * KS_ST
                                                 + kc * 16 + k_lcof) * 2);
                    mma_f16(&sacc[ntp * 2][0],     qf[kc][0], &kf[0]);
                    mma_f16(&sacc[ntp * 2][4],     qf[kc][1], &kf[0]);
                    mma_f16(&sacc[ntp * 2 + 1][0], qf[kc][0], &kf[2]);
                    mma_f16(&sacc[ntp * 2 + 1][4], qf[kc][1], &kf[2]);
                }
            }

            // ---- causal mask (diagonal tiles only) ----
            if (kt >= 4 * qt) {
                const int dq0 = qt * QROWS + warp * 32 + g - kt * 64;
#pragma unroll
                for (int nt = 0; nt < 8; nt++) {
                    const int k0 = nt * 8 + 2 * tig;
#pragma unroll
                    for (int mf = 0; mf < 2; mf++) {
                        const int r_lo = dq0 + mf * 16;
                        if (k0     > r_lo)      sacc[nt][mf * 4 + 0] = -1e30f;
                        if (k0 + 1 > r_lo)      sacc[nt][mf * 4 + 1] = -1e30f;
                        if (k0     > r_lo + 8)  sacc[nt][mf * 4 + 2] = -1e30f;
                        if (k0 + 1 > r_lo + 8)  sacc[nt][mf * 4 + 3] = -1e30f;
                    }
                }
            }

            // ---- online softmax (4 row groups: g, g+8, g+16, g+24) ----
            float mx[4];
#pragma unroll
            for (int i = 0; i < 4; i++) mx[i] = -1e30f;
#pragma unroll
            for (int nt = 0; nt < 8; nt++) {
                mx[0] = fmaxf(mx[0], fmaxf(sacc[nt][0], sacc[nt][1]));
                mx[1] = fmaxf(mx[1], fmaxf(sacc[nt][2], sacc[nt][3]));
                mx[2] = fmaxf(mx[2], fmaxf(sacc[nt][4], sacc[nt][5]));
                mx[3] = fmaxf(mx[3], fmaxf(sacc[nt][6], sacc[nt][7]));
            }
            float sc[4];
#pragma unroll
            for (int i = 0; i < 4; i++) {
                mx[i] = fmaxf(mx[i], __shfl_xor_sync(0xffffffffu, mx[i], 1));
                mx[i] = fmaxf(mx[i], __shfl_xor_sync(0xffffffffu, mx[i], 2));
                const float nm = fmaxf(m[i], mx[i]);
                sc[i] = fexp2(m[i] - nm);
                m[i] = nm;
                l[i] *= sc[i];
            }
#pragma unroll
            for (int nt = 0; nt < 8; nt++) {
                oacc[nt][0] *= sc[0]; oacc[nt][1] *= sc[0];
                oacc[nt][2] *= sc[1]; oacc[nt][3] *= sc[1];
                oacc[nt][4] *= sc[2]; oacc[nt][5] *= sc[2];
                oacc[nt][6] *= sc[3]; oacc[nt][7] *= sc[3];
            }

            // ---- P = exp2(S - m) -> fp16 per-warp smem ----
#pragma unroll
            for (int nt = 0; nt < 8; nt++) {
                const int c = nt * 8 + 2 * tig;
                const float p0 = fexp2(sacc[nt][0] - m[0]);
                const float p1 = fexp2(sacc[nt][1] - m[0]);
                const float p2 = fexp2(sacc[nt][2] - m[1]);
                const float p3 = fexp2(sacc[nt][3] - m[1]);
                const float p4 = fexp2(sacc[nt][4] - m[2]);
                const float p5 = fexp2(sacc[nt][5] - m[2]);
                const float p6 = fexp2(sacc[nt][6] - m[3]);
                const float p7 = fexp2(sacc[nt][7] - m[3]);
                l[0] += p0 + p1; l[1] += p2 + p3;
                l[2] += p4 + p5; l[3] += p6 + p7;
                *(__half2*)&Ps[(g)      * PS_ST + c] = __floats2half2_rn(p0, p1);
                *(__half2*)&Ps[(g + 8)  * PS_ST + c] = __floats2half2_rn(p2, p3);
                *(__half2*)&Ps[(g + 16) * PS_ST + c] = __floats2half2_rn(p4, p5);
                *(__half2*)&Ps[(g + 24) * PS_ST + c] = __floats2half2_rn(p6, p7);
            }
            __syncwarp();

            // ---- O += P @ V ----
#pragma unroll
            for (int kc = 0; kc < 4; kc++) {
                unsigned pa[2][4];
#pragma unroll
                for (int mi = 0; mi < 2; mi++)
                    ldsm_x4(pa[mi],
                            ps_base + (unsigned)((mi * 16 + a_lrow) * PS_ST
                                                 + kc * 16 + a_lcof) * 2);
#pragma unroll
                for (int np = 0; np < 4; np++) {
                    unsigned vf[4];
                    ldsm_x4_t(vf, vsu + (unsigned)((kc * 16 + v_lrow) * VS_ST
                                                   + np * 16 + v_ncof) * 2);
                    mma_f16(&oacc[np * 2][0],     pa[0], &vf[0]);
                    mma_f16(&oacc[np * 2][4],     pa[1], &vf[0]);
                    mma_f16(&oacc[np * 2 + 1][0], pa[0], &vf[2]);
                    mma_f16(&oacc[np * 2 + 1][4], pa[1], &vf[2]);
                }
            }
        }
        __syncthreads();
    }

    // ---- finalize ----
    float inv[4];
#pragma unroll
    for (int i = 0; i < 4; i++) {
        l[i] += __shfl_xor_sync(0xffffffffu, l[i], 1);
        l[i] += __shfl_xor_sync(0xffffffffu, l[i], 2);
        inv[i] = 1.f / l[i];
    }

    const int q0 = qt * QROWS + warp * 32 + g;
    __half* O0 = g_Oh + (size_t)(b * SS + q0)      * DD + h * DHD;
    __half* O1 = g_Oh + (size_t)(b * SS + q0 + 8)  * DD + h * DHD;
    __half* O2 = g_Oh + (size_t)(b * SS + q0 + 16) * DD + h * DHD;
    __half* O3 = g_Oh + (size_t)(b * SS + q0 + 24) * DD + h * DHD;
#pragma unroll
    for (int nt = 0; nt < 8; nt++) {
        const int c = nt * 8 + 2 * tig;
        *(__half2*)(O0 + c) = __floats2half2_rn(oacc[nt][0] * inv[0], oacc[nt][1] * inv[0]);
        *(__half2*)(O1 + c) = __floats2half2_rn(oacc[nt][2] * inv[1], oacc[nt][3] * inv[1]);
        *(__half2*)(O2 + c) = __floats2half2_rn(oacc[nt][4] * inv[2], oacc[nt][5] * inv[2]);
        *(__half2*)(O3 + c) = __floats2half2_rn(oacc[nt][6] * inv[3], oacc[nt][7] * inv[3]);
    }
}

// ---------------------------------------------------------------------------
// LayerNorm (no affine), eps=1e-5.
// ---------------------------------------------------------------------------
__global__ void __launch_bounds__(256)
ln_kernel(float* __restrict__ out)
{
    const int row = blockIdx.x;
    const float4 v = ((const float4*)(g_Y + (size_t)row * DD))[threadIdx.x];

    float s  = v.x + v.y + v.z + v.w;
    float s2 = v.x * v.x + v.y * v.y + v.z * v.z + v.w * v.w;

#pragma unroll
    for (int o = 16; o; o >>= 1) {
        s  += __shfl_xor_sync(0xffffffffu, s,  o);
        s2 += __shfl_xor_sync(0xffffffffu, s2, o);
    }

    __shared__ float sa[8], sb[8];
    const int wid  = threadIdx.x >> 5;
    const int lane = threadIdx.x & 31;
    if (lane == 0) { sa[wid] = s; sb[wid] = s2; }
    __syncthreads();

    s = 0.f; s2 = 0.f;
#pragma unroll
    for (int i = 0; i < 8; i++) { s += sa[i]; s2 += sb[i]; }

    const float mean = s * (1.f / DD);
    const float var  = s2 * (1.f / DD) - mean * mean;
    const float rstd = rsqrtf(var + 1e-5f);

    float4 o;
    o.x = (v.x - mean) * rstd;
    o.y = (v.y - mean) * rstd;
    o.z = (v.z - mean) * rstd;
    o.w = (v.w - mean) * rstd;
    ((float4*)(out + (size_t)row * DD))[threadIdx.x] = o;
}

// ---------------------------------------------------------------------------
// Launch
// ---------------------------------------------------------------------------
extern "C" void kernel_launch(void* const* d_in, const int* in_sizes, int n_in,
                              void* d_out, int out_size)
{
    (void)in_sizes; (void)n_in; (void)out_size;
    const float* x0 = (const float*)d_in[0];
    const float* Wi = (const float*)d_in[1];
    const float* Wo = (const float*)d_in[2];
    float* out = (float*)d_out;

    cudaFuncSetAttribute(attn_mma, cudaFuncAttributeMaxDynamicSharedMemorySize,
                         ATTN_SMEM_BYTES);
    cudaFuncSetAttribute(gemm_f16<0>, cudaFuncAttributeMaxDynamicSharedMemorySize,
                         GEMM_SMEM_BYTES);
    cudaFuncSetAttribute(gemm_f16<1>, cudaFuncAttributeMaxDynamicSharedMemorySize,
                         GEMM_SMEM_BYTES);

    __half* xh;  cudaGetSymbolAddress((void**)&xh,  g_Xh);
    __half* oh;  cudaGetSymbolAddress((void**)&oh,  g_Oh);
    __half* wih; cudaGetSymbolAddress((void**)&wih, g_WiTh);
    __half* woh; cudaGetSymbolAddress((void**)&woh, g_WoTh);

    transpose_cvt<<<dim3(D3 / 32, DD / 32), dim3(32, 8)>>>(Wi, wih, DD, D3);
    transpose_cvt<<<dim3(DD / 32, DD / 32), dim3(32, 8)>>>(Wo, woh, DD, DD);
    f2h<<<MTOK * DD / 1024, 256>>>(x0, xh);

    gemm_f16<0><<<dim3(D3 / 256, MTOK / 128), 256, GEMM_SMEM_BYTES>>>(
        xh, wih, nullptr, MTOK, D3, DD);
    attn_mma<<<dim3(SS / QROWS, HH, BB), 256, ATTN_SMEM_BYTES>>>();
    gemm_f16<1><<<dim3(DD / 256, MTOK / 128), 256, GEMM_SMEM_BYTES>>>(
        oh, woh, x0, MTOK, DD, DD);
    ln_kernel<<<MTOK, 256>>>(out);
}

// round 17
// speedup vs baseline: 1.0966x; 1.0966x over previous
#include <cuda_runtime.h>
#include <cuda_fp16.h>
#include <cstdint>

// Problem shape (fixed by the dataset)
#define BB   4
#define SS   2048
#define DD   1024
#define HH   16
#define DHD  64
#define D3   3072
#define MTOK (BB*SS)   // 8192 tokens

// Scratch (allocation-free: __device__ globals)
__device__ __half g_Qh[BB*HH*SS*DHD];
__device__ __half g_Kh[BB*HH*SS*DHD];
__device__ __half g_Vh[BB*HH*SS*DHD];
__device__ __half g_Oh[MTOK*DD];    // attention output (fp16)
__device__ float  g_Y[MTOK*DD];     // o-proj + residual (fp32)
__device__ __half g_Xh[MTOK*DD];    // fp16 copy of x0
__device__ __half g_WiTh[D3*DD];    // fp16 W_in^T  [N=3072][K=1024]
__device__ __half g_WoTh[DD*DD];    // fp16 W_o^T   [N=1024][K=1024]

// ---------------------------------------------------------------------------
// helpers
// ---------------------------------------------------------------------------
__device__ __forceinline__ void cp16(unsigned smem_addr, const void* gptr) {
    asm volatile("cp.async.cg.shared.global [%0], [%1], 16;\n"
                 :: "r"(smem_addr), "l"(gptr));
}
__device__ __forceinline__ void cp_commit() {
    asm volatile("cp.async.commit_group;\n");
}
template<int N>
__device__ __forceinline__ void cp_wait() {
    asm volatile("cp.async.wait_group %0;\n" :: "n"(N));
}
// fp16 MMA: m16n8k16, fp32 accumulate.
__device__ __forceinline__ void mma_f16(float* d,
                                        const unsigned* a, const unsigned* b)
{
    asm volatile(
        "mma.sync.aligned.m16n8k16.row.col.f32.f16.f16.f32 "
        "{%0,%1,%2,%3}, {%4,%5,%6,%7}, {%8,%9}, {%0,%1,%2,%3};"
        : "+f"(d[0]), "+f"(d[1]), "+f"(d[2]), "+f"(d[3])
        : "r"(a[0]), "r"(a[1]), "r"(a[2]), "r"(a[3]),
          "r"(b[0]), "r"(b[1]));
}
__device__ __forceinline__ void ldsm_x4(unsigned* r, unsigned addr) {
    asm volatile(
        "ldmatrix.sync.aligned.m8n8.x4.shared.b16 {%0,%1,%2,%3}, [%4];"
        : "=r"(r[0]), "=r"(r[1]), "=r"(r[2]), "=r"(r[3]) : "r"(addr));
}
__device__ __forceinline__ void ldsm_x4_t(unsigned* r, unsigned addr) {
    asm volatile(
        "ldmatrix.sync.aligned.m8n8.x4.trans.shared.b16 {%0,%1,%2,%3}, [%4];"
        : "=r"(r[0]), "=r"(r[1]), "=r"(r[2]), "=r"(r[3]) : "r"(addr));
}
__device__ __forceinline__ float fexp2(float x) {
    float r;
    asm("ex2.approx.f32 %0, %1;" : "=f"(r) : "f"(x));
    return r;
}
#define QSCALE 0.18033688f   // 0.125 * log2(e): softmax in base-2 domain

// ---------------------------------------------------------------------------
// conversion kernels
// ---------------------------------------------------------------------------
__global__ void f2h(const float* __restrict__ in, __half* __restrict__ out)
{
    const int i = blockIdx.x * 256 + threadIdx.x;
    float4 v = ((const float4*)in)[i];
    ((__half2*)out)[i * 2]     = __floats2half2_rn(v.x, v.y);
    ((__half2*)out)[i * 2 + 1] = __floats2half2_rn(v.z, v.w);
}

// W[K][N] fp32 row-major -> Wt[N][K] fp16
__global__ void transpose_cvt(const float* __restrict__ W, __half* __restrict__ Wt,
                              int K, int N)
{
    __shared__ float t[32][33];
    const int k0 = blockIdx.y * 32;
    const int n0 = blockIdx.x * 32;
    const int tx = threadIdx.x;
#pragma unroll
    for (int i = threadIdx.y; i < 32; i += 8)
        t[i][tx] = W[(size_t)(k0 + i) * N + n0 + tx];
    __syncthreads();
#pragma unroll
    for (int i = threadIdx.y; i < 32; i += 8)
        Wt[(size_t)(n0 + i) * K + k0 + tx] = __float2half(t[tx][i]);
}

// ---------------------------------------------------------------------------
// fp16 tensor-core GEMM: C[M,N] = A @ B, A[M][K] and Bt[N][K] fp16 k-major.
// R15 shape: block 128x128, 8 warps (2x4), warp tile 64x32, K-tile 32,
// 3-stage cp.async ring, prefetch distance 2, ONE barrier/ktile.
// NEW: all 12 LDSM for the k-tile hoisted ahead of all 32 MMAs (ILP).
// __launch_bounds__(256,2) pins regs <= 128 -> 2 blocks/SM (16 warps).
// ---------------------------------------------------------------------------
#define GH_ST 40
#define GEMM_SMEM_BYTES (3 * 2 * 128 * GH_ST * 2)   // 61,440 B

template<int MODE>
__global__ void __launch_bounds__(256, 2)
gemm_f16(const __half* __restrict__ A, const __half* __restrict__ Bt,
         const float* __restrict__ R, int M, int N, int K)
{
    extern __shared__ __half smh[];
    __half* As = smh;                          // 3 stages x 128*GH_ST halves
    __half* Bs = smh + 3 * 128 * GH_ST;

    const int tid    = threadIdx.x;
    const int warp   = tid >> 5;
    const int lane   = tid & 31;
    const int g      = lane >> 2;
    const int tig    = lane & 3;
    const int warp_m = warp >> 2;
    const int warp_n = warp & 3;
    const int row_w  = warp_m * 64;
    const int col_w  = warp_n * 32;

    const int bm = blockIdx.y * 128;
    const int bn = blockIdx.x * 128;

    const unsigned as_base = (unsigned)__cvta_generic_to_shared(As);
    const unsigned bs_base = (unsigned)__cvta_generic_to_shared(Bs);

    const int a_lrow = row_w + (lane & 15);
    const int a_lcof = (lane >> 4) * 8;                      // halves
    const int b_lrow = col_w + ((lane >> 4) << 3) + (lane & 7);
    const int b_lcof = ((lane >> 3) & 1) * 8;                // halves

    float acc[4][4][4];
#pragma unroll
    for (int mi = 0; mi < 4; mi++)
#pragma unroll
        for (int ni = 0; ni < 4; ni++)
#pragma unroll
            for (int r = 0; r < 4; r++) acc[mi][ni][r] = 0.f;

    auto prefetch = [&](int stage, int k0) {
        // A: 128 rows x 32 halves = 512 cp16; 2 per thread
#pragma unroll
        for (int t = 0; t < 2; t++) {
            const int idx = tid + t * 256;
            const int r   = idx >> 2;
            const int c   = (idx & 3) * 8;
            cp16(as_base + (unsigned)((stage * 128 + r) * GH_ST + c) * 2,
                 A + (size_t)(bm + r) * K + k0 + c);
        }
#pragma unroll
        for (int t = 0; t < 2; t++) {
            const int idx = tid + t * 256;
            const int r   = idx >> 2;
            const int c   = (idx & 3) * 8;
            cp16(bs_base + (unsigned)((stage * 128 + r) * GH_ST + c) * 2,
                 Bt + (size_t)(bn + r) * K + k0 + c);
        }
        cp_commit();
    };

    const int KT = K / 32;
    prefetch(0, 0);
    prefetch(1, 32);

    int buf = 0;
    for (int kt = 0; kt < KT; kt++) {
        cp_wait<1>();
        __syncthreads();

        if (kt + 2 < KT) {
            int nb = buf + 2; if (nb >= 3) nb -= 3;
            prefetch(nb, (kt + 2) * 32);
        } else {
            cp_commit();
        }

        const unsigned asu = as_base + (unsigned)(buf * 128 * GH_ST) * 2;
        const unsigned bsu = bs_base + (unsigned)(buf * 128 * GH_ST) * 2;

        // ---- hoist ALL fragment loads for both ks-chunks ----
        unsigned af[2][4][4];   // [ks-chunk][mi][reg]
        unsigned bf[2][2][4];   // [ks-chunk][nip][reg]
#pragma unroll
        for (int kc = 0; kc < 2; kc++) {
#pragma unroll
            for (int mi = 0; mi < 4; mi++)
                ldsm_x4(af[kc][mi],
                        asu + (unsigned)((a_lrow + mi * 16) * GH_ST
                                         + kc * 16 + a_lcof) * 2);
#pragma unroll
            for (int nip = 0; nip < 2; nip++)
                ldsm_x4(bf[kc][nip],
                        bsu + (unsigned)((b_lrow + nip * 16) * GH_ST
                                         + kc * 16 + b_lcof) * 2);
        }
        // ---- 32 MMAs back-to-back ----
#pragma unroll
        for (int kc = 0; kc < 2; kc++) {
#pragma unroll
            for (int mi = 0; mi < 4; mi++) {
#pragma unroll
                for (int nip = 0; nip < 2; nip++) {
                    mma_f16(acc[mi][nip * 2],     af[kc][mi], &bf[kc][nip][0]);
                    mma_f16(acc[mi][nip * 2 + 1], af[kc][mi], &bf[kc][nip][2]);
                }
            }
        }
        if (++buf == 3) buf = 0;
    }

    if (MODE == 0) {
        // fp16 scatter: pairs never straddle a Q/K/V segment (boundaries %64)
#pragma unroll
        for (int mi = 0; mi < 4; mi++) {
#pragma unroll
            for (int ni = 0; ni < 4; ni++) {
#pragma unroll
                for (int rr = 0; rr < 2; rr++) {
                    const int row = bm + row_w + mi * 16 + g + rr * 8;
                    const int bb  = row >> 11;
                    const int sl  = row & 2047;
                    const int e   = bn + col_w + ni * 8 + 2 * tig;
                    const int hh  = e / 192;
                    const int r   = e - hh * 192;
                    const int base = ((bb * HH + hh) * SS + sl) * DHD;
                    const __half2 v = __floats2half2_rn(acc[mi][ni][rr * 2 + 0],
                                                        acc[mi][ni][rr * 2 + 1]);
                    if (r < 64)        *(__half2*)&g_Qh[base + r]       = v;
                    else if (r < 128)  *(__half2*)&g_Kh[base + r - 64]  = v;
                    else               *(__half2*)&g_Vh[base + r - 128] = v;
                }
            }
        }
    } else {
#pragma unroll
        for (int mi = 0; mi < 4; mi++) {
#pragma unroll
            for (int ni = 0; ni < 4; ni++) {
#pragma unroll
                for (int rr = 0; rr < 2; rr++) {
                    const int row = bm + row_w + mi * 16 + g + rr * 8;
                    const int col = bn + col_w + ni * 8 + 2 * tig;
                    float2 rv = *(const float2*)(R + (size_t)row * DD + col);
                    float2 o;
                    o.x = acc[mi][ni][rr * 2 + 0] + rv.x;
                    o.y = acc[mi][ni][rr * 2 + 1] + rv.y;
                    *(float2*)(g_Y + (size_t)row * DD + col) = o;
                }
            }
        }
    }
}

// ---------------------------------------------------------------------------
// fp16 MMA flash attention, causal, base-2 softmax (fp32 accum/softmax).
// 256 threads, 8 warps x 32 q-rows (256 q-rows/block), K-tile 64 keys,
// 2-stage cp.async. All fragments via ldmatrix (V via .trans).
// (R15-passing, unchanged)
// ---------------------------------------------------------------------------
#define KS_ST 72
#define VS_ST 72
#define PS_ST 72
#define QROWS 256
#define ATTN_SMEM_BYTES ((2*64*KS_ST + 2*64*VS_ST + 8*32*PS_ST) * 2)

__global__ void __launch_bounds__(256, 1)
attn_mma()
{
    extern __shared__ __half smha[];
    __half* Ks0 = smha;                           // also stages Q (128*KS_ST)
    __half* Vs0 = smha + 2 * 64 * KS_ST;
    __half* Ps  = smha + 2 * 64 * KS_ST + 2 * 64 * VS_ST
                       + (threadIdx.x >> 5) * 32 * PS_ST;

    const int b    = blockIdx.z;
    const int h    = blockIdx.y;
    const int qt   = gridDim.x - 1 - blockIdx.x;   // heavy blocks first
    const int tid  = threadIdx.x;
    const int warp = tid >> 5;                     // 0..7
    const int lane = tid & 31;
    const int g    = lane >> 2;
    const int tig  = lane & 3;

    const __half* Qp = g_Qh + (size_t)(b * HH + h) * SS * DHD;
    const __half* Kp = g_Kh + (size_t)(b * HH + h) * SS * DHD;
    const __half* Vp = g_Vh + (size_t)(b * HH + h) * SS * DHD;

    const unsigned ks_base = (unsigned)__cvta_generic_to_shared(Ks0);
    const unsigned vs_base = (unsigned)__cvta_generic_to_shared(Vs0);
    const unsigned ps_base = (unsigned)__cvta_generic_to_shared(Ps);

    const int a_lrow = lane & 15;                          // A frags (Q, P)
    const int a_lcof = (lane >> 4) * 8;
    const int k_lrow = ((lane >> 4) << 3) + (lane & 7);    // K B-frags
    const int k_lcof = ((lane >> 3) & 1) * 8;
    const int v_lrow = (lane & 7) + ((lane >> 3) & 1) * 8; // V B-frags (.trans)
    const int v_ncof = (lane >> 4) * 8;

    // ---- stage Q (two 128-row passes through K buffer), pre-scaled fp16 ----
    unsigned qf[4][2][4];    // [k-chunk][mi][reg]
#pragma unroll
    for (int phase = 0; phase < 2; phase++) {
        __half* Qs = Ks0;    // 128 * KS_ST halves = the 2-stage K region
#pragma unroll
        for (int t = 0; t < 8; t++) {
            const int idx = tid + t * 256;
            const int r   = idx >> 4;
            const int c   = (idx & 15) << 2;
            const __half2* src = (const __half2*)(Qp +
                (size_t)(qt * QROWS + phase * 128 + r) * DHD + c);
            __half2 h0 = src[0], h1 = src[1];
            float2 f0 = __half22float2(h0), f1 = __half22float2(h1);
            *(__half2*)&Qs[r * KS_ST + c]     = __floats2half2_rn(f0.x * QSCALE, f0.y * QSCALE);
            *(__half2*)&Qs[r * KS_ST + c + 2] = __floats2half2_rn(f1.x * QSCALE, f1.y * QSCALE);
        }
        __syncthreads();
        if ((warp >> 2) == phase) {
            const int r0 = (warp & 3) * 32;
#pragma unroll
            for (int kc = 0; kc < 4; kc++)
#pragma unroll
                for (int mi = 0; mi < 2; mi++)
                    ldsm_x4(qf[kc][mi],
                            ks_base + (unsigned)((r0 + mi * 16 + a_lrow) * KS_ST
                                                 + kc * 16 + a_lcof) * 2);
        }
        __syncthreads();
    }

    auto prefetch = [&](int stage, int kt) {
#pragma unroll
        for (int t = 0; t < 2; t++) {
            const int idx = tid + t * 256;
            const int r   = idx >> 3;
            const int c   = (idx & 7) * 8;
            cp16(ks_base + (unsigned)(stage * 64 * KS_ST + r * KS_ST + c) * 2,
                 Kp + (size_t)(kt * 64 + r) * DHD + c);
        }
#pragma unroll
        for (int t = 0; t < 2; t++) {
            const int idx = tid + t * 256;
            const int r   = idx >> 3;
            const int c   = (idx & 7) * 8;
            cp16(vs_base + (unsigned)(stage * 64 * VS_ST + r * VS_ST + c) * 2,
                 Vp + (size_t)(kt * 64 + r) * DHD + c);
        }
        cp_commit();
    };

    float oacc[8][8];
#pragma unroll
    for (int nt = 0; nt < 8; nt++)
#pragma unroll
        for (int r = 0; r < 8; r++) oacc[nt][r] = 0.f;

    float m[4], l[4];
#pragma unroll
    for (int i = 0; i < 4; i++) { m[i] = -1e30f; l[i] = 0.f; }

    const int kt_end = 4 * qt + 3;                 // inclusive
    prefetch(0, 0);

    for (int kt = 0; kt <= kt_end; kt++) {
        if (kt < kt_end) prefetch((kt + 1) & 1, kt + 1);
        else             cp_commit();
        cp_wait<1>();
        __syncthreads();

        const bool active = (kt * 64 <= qt * QROWS + warp * 32 + 31);
        if (active) {
            const unsigned ksu = ks_base + (unsigned)((kt & 1) * 64 * KS_ST) * 2;
            const unsigned vsu = vs_base + (unsigned)((kt & 1) * 64 * VS_ST) * 2;

            float sacc[8][8];
#pragma unroll
            for (int nt = 0; nt < 8; nt++)
#pragma unroll
                for (int r = 0; r < 8; r++) sacc[nt][r] = 0.f;

            // ---- S = Q @ K^T ----
#pragma unroll
            for (int kc = 0; kc < 4; kc++) {
#pragma unroll
                for (int ntp = 0; ntp < 4; ntp++) {
                    unsigned kf[4];
                    ldsm_x4(kf, ksu + (unsigned)((ntp * 16 + k_lrow) * KS_ST
                                                 + kc * 16 + k_lcof) * 2);
                    mma_f16(&sacc[ntp * 2][0],     qf[kc][0], &kf[0]);
                    mma_f16(&sacc[ntp * 2][4],     qf[kc][1], &kf[0]);
                    mma_f16(&sacc[ntp * 2 + 1][0], qf[kc][0], &kf[2]);
                    mma_f16(&sacc[ntp * 2 + 1][4], qf[kc][1], &kf[2]);
                }
            }

            // ---- causal mask (diagonal tiles only) ----
            if (kt >= 4 * qt) {
                const int dq0 = qt * QROWS + warp * 32 + g - kt * 64;
#pragma unroll
                for (int nt = 0; nt < 8; nt++) {
                    const int k0 = nt * 8 + 2 * tig;
#pragma unroll
                    for (int mf = 0; mf < 2; mf++) {
                        const int r_lo = dq0 + mf * 16;
                        if (k0     > r_lo)      sacc[nt][mf * 4 + 0] = -1e30f;
                        if (k0 + 1 > r_lo)      sacc[nt][mf * 4 + 1] = -1e30f;
                        if (k0     > r_lo + 8)  sacc[nt][mf * 4 + 2] = -1e30f;
                        if (k0 + 1 > r_lo + 8)  sacc[nt][mf * 4 + 3] = -1e30f;
                    }
                }
            }

            // ---- online softmax (4 row groups: g, g+8, g+16, g+24) ----
            float mx[4];
#pragma unroll
            for (int i = 0; i < 4; i++) mx[i] = -1e30f;
#pragma unroll
            for (int nt = 0; nt < 8; nt++) {
                mx[0] = fmaxf(mx[0], fmaxf(sacc[nt][0], sacc[nt][1]));
                mx[1] = fmaxf(mx[1], fmaxf(sacc[nt][2], sacc[nt][3]));
                mx[2] = fmaxf(mx[2], fmaxf(sacc[nt][4], sacc[nt][5]));
                mx[3] = fmaxf(mx[3], fmaxf(sacc[nt][6], sacc[nt][7]));
            }
            float sc[4];
#pragma unroll
            for (int i = 0; i < 4; i++) {
                mx[i] = fmaxf(mx[i], __shfl_xor_sync(0xffffffffu, mx[i], 1));
                mx[i] = fmaxf(mx[i], __shfl_xor_sync(0xffffffffu, mx[i], 2));
                const float nm = fmaxf(m[i], mx[i]);
                sc[i] = fexp2(m[i] - nm);
                m[i] = nm;
                l[i] *= sc[i];
            }
#pragma unroll
            for (int nt = 0; nt < 8; nt++) {
                oacc[nt][0] *= sc[0]; oacc[nt][1] *= sc[0];
                oacc[nt][2] *= sc[1]; oacc[nt][3] *= sc[1];
                oacc[nt][4] *= sc[2]; oacc[nt][5] *= sc[2];
                oacc[nt][6] *= sc[3]; oacc[nt][7] *= sc[3];
            }

            // ---- P = exp2(S - m) -> fp16 per-warp smem ----
#pragma unroll
            for (int nt = 0; nt < 8; nt++) {
                const int c = nt * 8 + 2 * tig;
                const float p0 = fexp2(sacc[nt][0] - m[0]);
                const float p1 = fexp2(sacc[nt][1] - m[0]);
                const float p2 = fexp2(sacc[nt][2] - m[1]);
                const float p3 = fexp2(sacc[nt][3] - m[1]);
                const float p4 = fexp2(sacc[nt][4] - m[2]);
                const float p5 = fexp2(sacc[nt][5] - m[2]);
                const float p6 = fexp2(sacc[nt][6] - m[3]);
                const float p7 = fexp2(sacc[nt][7] - m[3]);
                l[0] += p0 + p1; l[1] += p2 + p3;
                l[2] += p4 + p5; l[3] += p6 + p7;
                *(__half2*)&Ps[(g)      * PS_ST + c] = __floats2half2_rn(p0, p1);
                *(__half2*)&Ps[(g + 8)  * PS_ST + c] = __floats2half2_rn(p2, p3);
                *(__half2*)&Ps[(g + 16) * PS_ST + c] = __floats2half2_rn(p4, p5);
                *(__half2*)&Ps[(g + 24) * PS_ST + c] = __floats2half2_rn(p6, p7);
            }
            __syncwarp();

            // ---- O += P @ V ----
#pragma unroll
            for (int kc = 0; kc < 4; kc++) {
                unsigned pa[2][4];
#pragma unroll
                for (int mi = 0; mi < 2; mi++)
                    ldsm_x4(pa[mi],
                            ps_base + (unsigned)((mi * 16 + a_lrow) * PS_ST
                                                 + kc * 16 + a_lcof) * 2);
#pragma unroll
                for (int np = 0; np < 4; np++) {
                    unsigned vf[4];
                    ldsm_x4_t(vf, vsu + (unsigned)((kc * 16 + v_lrow) * VS_ST
                                                   + np * 16 + v_ncof) * 2);
                    mma_f16(&oacc[np * 2][0],     pa[0], &vf[0]);
                    mma_f16(&oacc[np * 2][4],     pa[1], &vf[0]);
                    mma_f16(&oacc[np * 2 + 1][0], pa[0], &vf[2]);
                    mma_f16(&oacc[np * 2 + 1][4], pa[1], &vf[2]);
                }
            }
        }
        __syncthreads();
    }

    // ---- finalize ----
    float inv[4];
#pragma unroll
    for (int i = 0; i < 4; i++) {
        l[i] += __shfl_xor_sync(0xffffffffu, l[i], 1);
        l[i] += __shfl_xor_sync(0xffffffffu, l[i], 2);
        inv[i] = 1.f / l[i];
    }

    const int q0 = qt * QROWS + warp * 32 + g;
    __half* O0 = g_Oh + (size_t)(b * SS + q0)      * DD + h * DHD;
    __half* O1 = g_Oh + (size_t)(b * SS + q0 + 8)  * DD + h * DHD;
    __half* O2 = g_Oh + (size_t)(b * SS + q0 + 16) * DD + h * DHD;
    __half* O3 = g_Oh + (size_t)(b * SS + q0 + 24) * DD + h * DHD;
#pragma unroll
    for (int nt = 0; nt < 8; nt++) {
        const int c = nt * 8 + 2 * tig;
        *(__half2*)(O0 + c) = __floats2half2_rn(oacc[nt][0] * inv[0], oacc[nt][1] * inv[0]);
        *(__half2*)(O1 + c) = __floats2half2_rn(oacc[nt][2] * inv[1], oacc[nt][3] * inv[1]);
        *(__half2*)(O2 + c) = __floats2half2_rn(oacc[nt][4] * inv[2], oacc[nt][5] * inv[2]);
        *(__half2*)(O3 + c) = __floats2half2_rn(oacc[nt][6] * inv[3], oacc[nt][7] * inv[3]);
    }
}

// ---------------------------------------------------------------------------
// LayerNorm (no affine), eps=1e-5.
// ---------------------------------------------------------------------------
__global__ void __launch_bounds__(256)
ln_kernel(float* __restrict__ out)
{
    const int row = blockIdx.x;
    const float4 v = ((const float4*)(g_Y + (size_t)row * DD))[threadIdx.x];

    float s  = v.x + v.y + v.z + v.w;
    float s2 = v.x * v.x + v.y * v.y + v.z * v.z + v.w * v.w;

#pragma unroll
    for (int o = 16; o; o >>= 1) {
        s  += __shfl_xor_sync(0xffffffffu, s,  o);
        s2 += __shfl_xor_sync(0xffffffffu, s2, o);
    }

    __shared__ float sa[8], sb[8];
    const int wid  = threadIdx.x >> 5;
    const int lane = threadIdx.x & 31;
    if (lane == 0) { sa[wid] = s; sb[wid] = s2; }
    __syncthreads();

    s = 0.f; s2 = 0.f;
#pragma unroll
    for (int i = 0; i < 8; i++) { s += sa[i]; s2 += sb[i]; }

    const float mean = s * (1.f / DD);
    const float var  = s2 * (1.f / DD) - mean * mean;
    const float rstd = rsqrtf(var + 1e-5f);

    float4 o;
    o.x = (v.x - mean) * rstd;
    o.y = (v.y - mean) * rstd;
    o.z = (v.z - mean) * rstd;
    o.w = (v.w - mean) * rstd;
    ((float4*)(out + (size_t)row * DD))[threadIdx.x] = o;
}

// ---------------------------------------------------------------------------
// Launch
// ---------------------------------------------------------------------------
extern "C" void kernel_launch(void* const* d_in, const int* in_sizes, int n_in,
                              void* d_out, int out_size)
{
    (void)in_sizes; (void)n_in; (void)out_size;
    const float* x0 = (const float*)d_in[0];
    const float* Wi = (const float*)d_in[1];
    const float* Wo = (const float*)d_in[2];
    float* out = (float*)d_out;

    cudaFuncSetAttribute(attn_mma, cudaFuncAttributeMaxDynamicSharedMemorySize,
                         ATTN_SMEM_BYTES);
    cudaFuncSetAttribute(gemm_f16<0>, cudaFuncAttributeMaxDynamicSharedMemorySize,
                         GEMM_SMEM_BYTES);
    cudaFuncSetAttribute(gemm_f16<1>, cudaFuncAttributeMaxDynamicSharedMemorySize,
                         GEMM_SMEM_BYTES);

    __half* xh;  cudaGetSymbolAddress((void**)&xh,  g_Xh);
    __half* oh;  cudaGetSymbolAddress((void**)&oh,  g_Oh);
    __half* wih; cudaGetSymbolAddress((void**)&wih, g_WiTh);
    __half* woh; cudaGetSymbolAddress((void**)&woh, g_WoTh);

    transpose_cvt<<<dim3(D3 / 32, DD / 32), dim3(32, 8)>>>(Wi, wih, DD, D3);
    transpose_cvt<<<dim3(DD / 32, DD / 32), dim3(32, 8)>>>(Wo, woh, DD, DD);
    f2h<<<MTOK * DD / 1024, 256>>>(x0, xh);

    gemm_f16<0><<<dim3(D3 / 128, MTOK / 128), 256, GEMM_SMEM_BYTES>>>(
        xh, wih, nullptr, MTOK, D3, DD);
    attn_mma<<<dim3(SS / QROWS, HH, BB), 256, ATTN_SMEM_BYTES>>>();
    gemm_f16<1><<<dim3(DD / 128, MTOK / 128), 256, GEMM_SMEM_BYTES>>>(
        oh, woh, x0, MTOK, DD, DD);
    ln_kernel<<<MTOK, 256>>>(out);
}